// round 6
// baseline (speedup 1.0000x reference)
#include <cuda_runtime.h>
#include <math.h>

#define N_BATCH 16
#define CH 64
#define SCH 128
#define L_IN 8192
#define L_OUT 7682
#define TILE 128
#define NTH 256
#define NUM_BLOCKS 16

// Ping-pong residual buffers (allocation-free scratch).
__device__ float g_bufA[(size_t)N_BATCH * CH * L_IN];
__device__ float g_bufB[(size_t)N_BATCH * CH * L_IN];

// Duplicated weights: every scalar w stored as (w, w) -> ready f32x2 operand.
#define WD_SZ (CH * CH * 2)
#define WR_SZ (CH * CH)
#define WS_SZ (SCH * CH)
#define DUP_WD_BASE 0
#define DUP_WR_BASE (NUM_BLOCKS * WD_SZ * 2)
#define DUP_WS_BASE (DUP_WR_BASE + NUM_BLOCKS * WR_SZ * 2)
#define DUP_TOTAL   (DUP_WS_BASE + NUM_BLOCKS * WS_SZ * 2)
__device__ float g_wdup[DUP_TOTAL];

// Shared memory: only activations. 3 * 64 * 128 floats = 96 KB -> 2 CTAs/SM.
#define OFF_X0 0
#define OFF_X1 (CH * TILE)
#define OFF_G  (2 * CH * TILE)
#define SMEM_FLOATS (3 * CH * TILE)

typedef unsigned long long u64;

union F4U {
    float4 f;
    u64 u[2];
    float s[4];
};

// 8 consecutive floats viewed as 4 f32x2 pairs.
struct alignas(16) V8 {
    union {
        u64 u[4];
        float s[8];
        float2 f2[4];
        float4 f[2];
    };
};

__device__ __forceinline__ void ldv8(V8& v, const float* p) {
    v.f[0] = *(const float4*)p;
    v.f[1] = *(const float4*)(p + 4);
}

__device__ __forceinline__ u64 fma2(u64 a, u64 b, u64 c) {
    u64 d;
    asm("fma.rn.f32x2 %0, %1, %2, %3;" : "=l"(d) : "l"(a), "l"(b), "l"(c));
    return d;
}

// g = tanh(y) * sigmoid(y), via a = e^{-y}.
__device__ __forceinline__ float gated(float y) {
    float yc = fminf(fmaxf(y, -15.f), 15.f);
    float a = __expf(-yc);
    float a2 = a * a;
    return __fdividef(1.f - a2, (1.f + a2) * (1.f + a));
}

// One-shot weight duplication: out[2i] = out[2i+1] = in[i].
__global__ void dup_weights_kernel(const float* __restrict__ Wd,
                                   const float* __restrict__ Wr,
                                   const float* __restrict__ Ws)
{
    int idx = blockIdx.x * blockDim.x + threadIdx.x;
    const int nWd = NUM_BLOCKS * WD_SZ;
    const int nWr = NUM_BLOCKS * WR_SZ;
    const int nWs = NUM_BLOCKS * WS_SZ;
    float v; int base; int j;
    if (idx < nWd) { v = Wd[idx]; base = DUP_WD_BASE; j = idx; }
    else if (idx < nWd + nWr) { j = idx - nWd; v = Wr[j]; base = DUP_WR_BASE; }
    else if (idx < nWd + nWr + nWs) { j = idx - nWd - nWr; v = Ws[j]; base = DUP_WS_BASE; }
    else return;
    g_wdup[base + 2 * j]     = v;
    g_wdup[base + 2 * j + 1] = v;
}

__global__ void __launch_bounds__(NTH, 2)
wavenet_block_kernel(const float* __restrict__ src, int src_stride,
                     float* __restrict__ dst, int dst_stride,
                     const float* __restrict__ wd,
                     const float* __restrict__ wr,
                     const float* __restrict__ ws,
                     float* __restrict__ skip,
                     int Lcur, int d, int skip_off, int is_first)
{
    extern __shared__ float sm[];
    const int tid = threadIdx.x;
    const int n = blockIdx.y;
    const int l0 = blockIdx.x * TILE;
    const int Lnew = Lcur - d;

    // ---- stage the two input taps: X0[i][l]=src[l0+l], X1[i][l]=src[l0+l+d] ----
    const float* srcn = src + (size_t)n * CH * src_stride;
#pragma unroll
    for (int k = 0; k < (CH * TILE) / NTH; k++) {
        int idx = tid + k * NTH;
        int i = idx >> 7, l = idx & (TILE - 1);
        int p0 = l0 + l;
        int p1 = p0 + d;
        sm[OFF_X0 + idx] = (p0 < Lcur) ? srcn[(size_t)i * src_stride + p0] : 0.f;
        sm[OFF_X1 + idx] = (p1 < Lcur) ? srcn[(size_t)i * src_stride + p1] : 0.f;
    }
    __syncthreads();

    const int lt = (tid & 15) * 8;   // 8 consecutive positions (4 f32x2 pairs)
    const int ot = (tid >> 4) * 4;   // 4 consecutive output channels

    // ================= phase 1: dilated conv (64x64x2) + gated activation =================
    u64 acc[4][4];
#pragma unroll
    for (int a = 0; a < 4; a++)
#pragma unroll
        for (int q = 0; q < 4; q++) acc[a][q] = 0ull;

#pragma unroll 2
    for (int ii = 0; ii < CH; ii += 2) {
        V8 a0, b0, a1, b1;
        ldv8(a0, sm + OFF_X0 + ii * TILE + lt);
        ldv8(b0, sm + OFF_X1 + ii * TILE + lt);
        ldv8(a1, sm + OFF_X0 + (ii + 1) * TILE + lt);
        ldv8(b1, sm + OFF_X1 + (ii + 1) * TILE + lt);
#pragma unroll
        for (int oo = 0; oo < 4; oo++) {
            F4U w0, w1;
            w0.f = __ldg((const float4*)(wd + (ot + oo) * 256 + ii * 4));
            w1.f = __ldg((const float4*)(wd + (ot + oo) * 256 + ii * 4 + 4));
#pragma unroll
            for (int q = 0; q < 4; q++) {
                acc[oo][q] = fma2(a0.u[q], w0.u[0], acc[oo][q]);
                acc[oo][q] = fma2(b0.u[q], w0.u[1], acc[oo][q]);
                acc[oo][q] = fma2(a1.u[q], w1.u[0], acc[oo][q]);
                acc[oo][q] = fma2(b1.u[q], w1.u[1], acc[oo][q]);
            }
        }
    }
    // gated activation -> G[o][l]
#pragma unroll
    for (int oo = 0; oo < 4; oo++) {
        V8 g;
#pragma unroll
        for (int q = 0; q < 4; q++) g.u[q] = acc[oo][q];
#pragma unroll
        for (int k = 0; k < 8; k++) g.s[k] = gated(g.s[k]);
        float* gp = sm + OFF_G + (ot + oo) * TILE + lt;
        *(float4*)gp = g.f[0];
        *(float4*)(gp + 4) = g.f[1];
    }
    __syncthreads();

    // ================= phase 2a: residual 1x1 conv + residual add =================
    u64 r[4][4];
#pragma unroll
    for (int oo = 0; oo < 4; oo++) {
        V8 x1;
        ldv8(x1, sm + OFF_X1 + (ot + oo) * TILE + lt);
#pragma unroll
        for (int q = 0; q < 4; q++) r[oo][q] = x1.u[q];
    }

#pragma unroll 2
    for (int ii = 0; ii < CH; ii += 4) {
        V8 g0, g1, g2, g3;
        ldv8(g0, sm + OFF_G + (ii + 0) * TILE + lt);
        ldv8(g1, sm + OFF_G + (ii + 1) * TILE + lt);
        ldv8(g2, sm + OFF_G + (ii + 2) * TILE + lt);
        ldv8(g3, sm + OFF_G + (ii + 3) * TILE + lt);
#pragma unroll
        for (int oo = 0; oo < 4; oo++) {
            F4U wA, wB;
            wA.f = __ldg((const float4*)(wr + (ot + oo) * 128 + ii * 2));
            wB.f = __ldg((const float4*)(wr + (ot + oo) * 128 + ii * 2 + 4));
#pragma unroll
            for (int q = 0; q < 4; q++) {
                r[oo][q] = fma2(g0.u[q], wA.u[0], r[oo][q]);
                r[oo][q] = fma2(g1.u[q], wA.u[1], r[oo][q]);
                r[oo][q] = fma2(g2.u[q], wB.u[0], r[oo][q]);
                r[oo][q] = fma2(g3.u[q], wB.u[1], r[oo][q]);
            }
        }
    }
    // direct store of residual output (float2 is safe here: dst_stride is even
    // and l0+lt is a multiple of 8 -> offsets always even -> 8B-aligned)
    {
        const bool full = (l0 + lt + 7 < Lnew);
#pragma unroll
        for (int oo = 0; oo < 4; oo++) {
            V8 rv;
#pragma unroll
            for (int q = 0; q < 4; q++) rv.u[q] = r[oo][q];
            float* drow = dst + ((size_t)n * CH + (ot + oo)) * dst_stride + l0 + lt;
            if (full) {
#pragma unroll
                for (int q = 0; q < 4; q++)
                    *(float2*)(drow + 2 * q) = rv.f2[q];
            } else {
#pragma unroll
                for (int k = 0; k < 8; k++)
                    if (l0 + lt + k < Lnew) drow[k] = rv.s[k];
            }
        }
    }

    // ================= phase 2b: skip 1x1 conv (128x64), two passes of 4 ch =================
    const int st = (tid >> 4) * 8;
#pragma unroll
    for (int half = 0; half < 2; half++) {
        u64 sk[4][4];
#pragma unroll
        for (int a = 0; a < 4; a++)
#pragma unroll
            for (int q = 0; q < 4; q++) sk[a][q] = 0ull;

#pragma unroll 2
        for (int ii = 0; ii < CH; ii += 4) {
            V8 g0, g1, g2, g3;
            ldv8(g0, sm + OFF_G + (ii + 0) * TILE + lt);
            ldv8(g1, sm + OFF_G + (ii + 1) * TILE + lt);
            ldv8(g2, sm + OFF_G + (ii + 2) * TILE + lt);
            ldv8(g3, sm + OFF_G + (ii + 3) * TILE + lt);
#pragma unroll
            for (int ss = 0; ss < 4; ss++) {
                F4U wA, wB;
                const float* wrow = ws + (st + half * 4 + ss) * 128;
                wA.f = __ldg((const float4*)(wrow + ii * 2));
                wB.f = __ldg((const float4*)(wrow + ii * 2 + 4));
#pragma unroll
                for (int q = 0; q < 4; q++) {
                    sk[ss][q] = fma2(g0.u[q], wA.u[0], sk[ss][q]);
                    sk[ss][q] = fma2(g1.u[q], wA.u[1], sk[ss][q]);
                    sk[ss][q] = fma2(g2.u[q], wB.u[0], sk[ss][q]);
                    sk[ss][q] = fma2(g3.u[q], wB.u[1], sk[ss][q]);
                }
            }
        }
        // skip accumulation directly in global. SCALAR accesses only: the skip
        // index j = p - skip_off has launch-dependent parity (skip_off is odd
        // for most blocks), so float2 here traps on misalignment.
        const int jbase = l0 + lt - skip_off;
        const bool full = (jbase >= 0) && (l0 + lt + 7 < Lnew);
#pragma unroll
        for (int ss = 0; ss < 4; ss++) {
            V8 sv;
#pragma unroll
            for (int q = 0; q < 4; q++) sv.u[q] = sk[ss][q];
            float* srow = skip + ((size_t)n * SCH + (st + half * 4 + ss)) * L_OUT;
            if (full) {
                if (is_first) {
#pragma unroll
                    for (int k = 0; k < 8; k++) srow[jbase + k] = sv.s[k];
                } else {
#pragma unroll
                    for (int k = 0; k < 8; k++) srow[jbase + k] += sv.s[k];
                }
            } else {
#pragma unroll
                for (int k = 0; k < 8; k++) {
                    int p = l0 + lt + k;
                    int j = p - skip_off;
                    if (p < Lnew && j >= 0) {
                        if (is_first) srow[j] = sv.s[k];
                        else          srow[j] += sv.s[k];
                    }
                }
            }
        }
    }
}

extern "C" void kernel_launch(void* const* d_in, const int* in_sizes, int n_in,
                              void* d_out, int out_size)
{
    const float* x  = (const float*)d_in[0];  // (16, 64, 8192)
    const float* Wd = (const float*)d_in[1];  // (16, 64, 64, 2)
    const float* Wr = (const float*)d_in[2];  // (16, 64, 64)
    const float* Ws = (const float*)d_in[3];  // (16, 128, 64)

    float* out  = (float*)d_out;                                   // (16, 64, 7682)
    float* skip = (float*)d_out + (size_t)N_BATCH * CH * L_OUT;    // (16, 128, 7682)

    float *bufA = nullptr, *bufB = nullptr, *wdup = nullptr;
    cudaGetSymbolAddress((void**)&bufA, g_bufA);
    cudaGetSymbolAddress((void**)&bufB, g_bufB);
    cudaGetSymbolAddress((void**)&wdup, g_wdup);
    cudaFuncSetAttribute(wavenet_block_kernel,
                         cudaFuncAttributeMaxDynamicSharedMemorySize,
                         SMEM_FLOATS * (int)sizeof(float));

    // duplicate all weights once per replay
    {
        int total = NUM_BLOCKS * (WD_SZ + WR_SZ + WS_SZ);
        dup_weights_kernel<<<(total + 255) / 256, 256>>>(Wd, Wr, Ws);
    }

    const int dil[NUM_BLOCKS] = {1, 2, 4, 8, 16, 32, 64, 128,
                                 1, 2, 4, 8, 16, 32, 64, 128};

    const float* src = x;
    int src_stride = L_IN;
    int Lcur = L_IN;

    for (int i = 0; i < NUM_BLOCKS; i++) {
        int d = dil[i];
        int Lnew = Lcur - d;
        float* dst;
        int dst_stride;
        if (i == NUM_BLOCKS - 1) { dst = out; dst_stride = L_OUT; }
        else                     { dst = (i & 1) ? bufB : bufA; dst_stride = L_IN; }

        dim3 grid((Lnew + TILE - 1) / TILE, N_BATCH);
        wavenet_block_kernel<<<grid, NTH, SMEM_FLOATS * sizeof(float)>>>(
            src, src_stride, dst, dst_stride,
            wdup + DUP_WD_BASE + (size_t)i * WD_SZ * 2,
            wdup + DUP_WR_BASE + (size_t)i * WR_SZ * 2,
            wdup + DUP_WS_BASE + (size_t)i * WS_SZ * 2,
            skip, Lcur, d, Lnew - L_OUT, (i == 0) ? 1 : 0);

        src = dst;
        src_stride = dst_stride;
        Lcur = Lnew;
    }
}